// round 11
// baseline (speedup 1.0000x reference)
#include <cuda_runtime.h>
#include <cuda_bf16.h>
#include <mma.h>
using namespace nvcuda;

#define NN   30000
#define NNP  30080           // padded rows (235 * 128) for unguarded wmma tiles
#define EE   960000
#define HID  128
#define LL   3
#define BB   64
#define NSHARD 16

typedef unsigned long long u64;
__device__ __forceinline__ u64 pk2(float lo, float hi) {
    u64 r; asm("mov.b64 %0, {%1, %2};" : "=l"(r) : "f"(lo), "f"(hi)); return r;
}
__device__ __forceinline__ void upk2(float& lo, float& hi, u64 v) {
    asm("mov.b64 {%0, %1}, %2;" : "=f"(lo), "=f"(hi) : "l"(v));
}
__device__ __forceinline__ u64 fma2(u64 a, u64 b, u64 c) {
    u64 d; asm("fma.rn.f32x2 %0, %1, %2, %3;" : "=l"(d) : "l"(a), "l"(b), "l"(c)); return d;
}
__device__ __forceinline__ u64 add2(u64 a, u64 b) {
    u64 d; asm("add.rn.f32x2 %0, %1, %2;" : "=l"(d) : "l"(a), "l"(b)); return d;
}

// ---------------- device scratch ----------------
__device__ __align__(16) float  g_h[NNP * HID];    // padding rows stay zero
__device__ __align__(16) float  g_xl[NNP * HID];
__device__ __align__(16) float  g_xr[NNP * HID];
__device__ __align__(16) float  g_g[NN * HID];
__device__ __align__(16) int    g_cnt[32768];      // padded for int4 scan
__device__ int    g_rowptr[NN + 1];
__device__ int    g_fill[NN];                      // seeded with row starts by k_scan
__device__ __align__(16) float4 g_csr[EE];
__device__ __align__(16) float  g_M[LL * 4 * HID]; // {ea0,ea1,ea2,const} per layer
__device__ __align__(16) float  g_bnsum[NSHARD * HID];
__device__ __align__(16) float  g_bnsq[NSHARD * HID];
__device__ __align__(16) float  g_z1[BB * 256];
__device__ __align__(16) float  g_z2[BB * 128];

// ---------------- h = x @ npW + npB; zero g_cnt; block 0 also does precM ----------------
__global__ void k_node_proj(const float* __restrict__ x,
                            const float* __restrict__ npW,
                            const float* __restrict__ npB,
                            const float* __restrict__ epW,
                            const float* __restrict__ epB,
                            const float* __restrict__ We)
{
    __shared__ float Ws[28 * HID];
    int tid = threadIdx.x;                    // 128
    int gtid = blockIdx.x * 128 + tid;        // 938*128 = 120064 >= 32768
    if (gtid < 32768) g_cnt[gtid] = 0;

    for (int i = tid; i < 28 * HID; i += 128) Ws[i] = npW[i];
    __syncthreads();
    float bias = npB[tid];
    int row0 = blockIdx.x * 32;
    for (int r = 0; r < 32; r++) {
        int row = row0 + r;
        if (row >= NN) break;
        const float* xr = x + row * 28;
        float acc = bias;
        #pragma unroll
        for (int k = 0; k < 28; k++) acc = fmaf(__ldg(xr + k), Ws[k * HID + tid], acc);
        g_h[row * HID + tid] = acc;
    }

    // block 0: precompute M[l] = epW @ We[l], const row = epB @ We[l]
    if (blockIdx.x == 0) {
        int c = tid;
        for (int l = 0; l < LL; l++) {
            const float* W = We + l * HID * HID;
            float m0 = 0.f, m1 = 0.f, m2 = 0.f, mc = 0.f;
            for (int k = 0; k < HID; k++) {
                float w = W[k * HID + c];
                m0 = fmaf(epW[0 * HID + k], w, m0);
                m1 = fmaf(epW[1 * HID + k], w, m1);
                m2 = fmaf(epW[2 * HID + k], w, m2);
                mc = fmaf(epB[k], w, mc);
            }
            g_M[l * 512 + 0 * HID + c] = m0;
            g_M[l * 512 + 1 * HID + c] = m1;
            g_M[l * 512 + 2 * HID + c] = m2;
            g_M[l * 512 + 3 * HID + c] = mc;
        }
    }
}

// ---------------- degree histogram: 4 edges/thread via int4 ----------------
__global__ void k_deg(const int* __restrict__ ei)
{
    int e4 = (blockIdx.x * blockDim.x + threadIdx.x) * 4;
    if (e4 >= EE) return;
    int4 d = *(const int4*)&ei[EE + e4];      // dst array is contiguous, 16B aligned
    atomicAdd(&g_cnt[d.x], 1);
    atomicAdd(&g_cnt[d.y], 1);
    atomicAdd(&g_cnt[d.z], 1);
    atomicAdd(&g_cnt[d.w], 1);
}

// ---------------- exclusive scan; also seeds g_fill with row starts ----------------
__global__ void k_scan()
{
    extern __shared__ int sst[];
    int* stage = sst;                         // 33792 ints (padded i + i/32)
    int* part  = sst + 33792;                 // 1024 ints
    int t = threadIdx.x;
    int base = t * 32;
    int vals[32];
    const int4* c4 = (const int4*)&g_cnt[base];
    int s = 0;
    #pragma unroll
    for (int q = 0; q < 8; q++) {
        int4 v = c4[q];
        vals[q * 4 + 0] = v.x; vals[q * 4 + 1] = v.y;
        vals[q * 4 + 2] = v.z; vals[q * 4 + 3] = v.w;
        s += v.x + v.y + v.z + v.w;
    }
    part[t] = s;
    __syncthreads();
    for (int off = 1; off < 1024; off <<= 1) {
        int v = (t >= off) ? part[t - off] : 0;
        __syncthreads();
        part[t] += v;
        __syncthreads();
    }
    int run = (t == 0) ? 0 : part[t - 1];
    #pragma unroll
    for (int q = 0; q < 32; q++) {
        int i = base + q;
        stage[i + (i >> 5)] = run;            // conflict-free scatter
        run += vals[q];
    }
    __syncthreads();
    for (int i = t; i <= NN; i += 1024) {
        int v = stage[i + (i >> 5)];
        g_rowptr[i] = v;
        if (i < NN) g_fill[i] = v;            // seed fill cursor with row start
    }
}

// ---------------- scatter edges into CSR: 2 edges/thread, single atomic each ----------------
__global__ void k_scatter(const int* __restrict__ ei, const float* __restrict__ ea)
{
    int t = blockIdx.x * blockDim.x + threadIdx.x;   // EE/2 threads
    int eA = t;
    int eB = t + EE / 2;
    if (eA >= EE / 2) return;
    int sA = __ldg(&ei[eA]);
    int dA = __ldg(&ei[EE + eA]);
    float a0 = __ldg(&ea[eA * 3 + 0]);
    float a1 = __ldg(&ea[eA * 3 + 1]);
    float a2 = __ldg(&ea[eA * 3 + 2]);
    int sB = __ldg(&ei[eB]);
    int dB = __ldg(&ei[EE + eB]);
    float b0 = __ldg(&ea[eB * 3 + 0]);
    float b1 = __ldg(&ea[eB * 3 + 1]);
    float b2 = __ldg(&ea[eB * 3 + 2]);
    int posA = atomicAdd(&g_fill[dA], 1);
    int posB = atomicAdd(&g_fill[dB], 1);
    g_csr[posA] = make_float4(__int_as_float(sA), a0, a1, a2);
    g_csr[posB] = make_float4(__int_as_float(sB), b0, b1, b2);
}

// ---------------- xl/xr GEMM: tf32 WMMA, 128x128 tile, 8 warps ----------------
__global__ void __launch_bounds__(256)
k_gemm(const float* __restrict__ W0, const float* __restrict__ b0,
       const float* __restrict__ W1, const float* __restrict__ b1)
{
    __shared__ __align__(16) float As[128][40];    // 128 rows x 32 k (tf32 values)
    __shared__ __align__(16) float Bs[32][132];    // 32 k x 128 cols (tf32 values)
    __shared__ __align__(16) float biasS[16][132]; // bias replicated over 16 rows
    const float* W  = blockIdx.z ? W1 : W0;
    const float* bv = blockIdx.z ? b1 : b0;
    float* out = blockIdx.z ? g_xr : g_xl;

    int tid = threadIdx.x;
    int wid = tid >> 5;
    int row0 = blockIdx.x * 128;

    if (blockIdx.x == 0 && blockIdx.z == 0) { // zero bn shard accumulators for this layer
        for (int i = tid; i < NSHARD * HID; i += 256) {
            g_bnsum[i] = 0.f; g_bnsq[i] = 0.f;
        }
    }

    for (int i = tid; i < 16 * 128; i += 256) {
        int r = i >> 7, c = i & 127;
        biasS[r][c] = bv[c];
    }
    __syncthreads();

    int wr = (wid >> 1) * 32;                 // warp row offset within tile
    int wc = (wid & 1) * 64;                  // warp col offset within tile

    wmma::fragment<wmma::accumulator, 16, 16, 8, float> c[2][4];
    #pragma unroll
    for (int i = 0; i < 2; i++)
        #pragma unroll
        for (int j = 0; j < 4; j++)
            wmma::load_matrix_sync(c[i][j], &biasS[0][wc + j * 16], 132, wmma::mem_row_major);

    for (int kb = 0; kb < HID; kb += 32) {
        __syncthreads();                      // previous iteration's frags consumed
        #pragma unroll
        for (int q = 0; q < 4; q++) {         // A: 128 rows x 32 k = 1024 float4
            int idx = tid + q * 256;
            int r = idx >> 3;
            int kk = (idx & 7) << 2;
            float4 v = *(const float4*)&g_h[(size_t)(row0 + r) * HID + kb + kk];
            As[r][kk + 0] = wmma::__float_to_tf32(v.x);
            As[r][kk + 1] = wmma::__float_to_tf32(v.y);
            As[r][kk + 2] = wmma::__float_to_tf32(v.z);
            As[r][kk + 3] = wmma::__float_to_tf32(v.w);
        }
        #pragma unroll
        for (int q = 0; q < 4; q++) {         // B: 32 k x 128 cols = 1024 float4
            int idx = tid + q * 256;
            int kk = idx >> 5;
            int cc = (idx & 31) << 2;
            float4 v = *(const float4*)&W[(kb + kk) * HID + cc];
            Bs[kk][cc + 0] = wmma::__float_to_tf32(v.x);
            Bs[kk][cc + 1] = wmma::__float_to_tf32(v.y);
            Bs[kk][cc + 2] = wmma::__float_to_tf32(v.z);
            Bs[kk][cc + 3] = wmma::__float_to_tf32(v.w);
        }
        __syncthreads();
        #pragma unroll
        for (int ks = 0; ks < 32; ks += 8) {
            wmma::fragment<wmma::matrix_a, 16, 16, 8, wmma::precision::tf32, wmma::row_major> a[2];
            wmma::fragment<wmma::matrix_b, 16, 16, 8, wmma::precision::tf32, wmma::row_major> b[4];
            #pragma unroll
            for (int i = 0; i < 2; i++)
                wmma::load_matrix_sync(a[i], &As[wr + i * 16][ks], 40);
            #pragma unroll
            for (int j = 0; j < 4; j++)
                wmma::load_matrix_sync(b[j], &Bs[ks][wc + j * 16], 132);
            #pragma unroll
            for (int i = 0; i < 2; i++)
                #pragma unroll
                for (int j = 0; j < 4; j++)
                    wmma::mma_sync(c[i][j], a[i], b[j], c[i][j]);
        }
    }
    #pragma unroll
    for (int i = 0; i < 2; i++)
        #pragma unroll
        for (int j = 0; j < 4; j++)
            wmma::store_matrix_sync(&out[(size_t)(row0 + wr + i * 16) * HID + wc + j * 16],
                                    c[i][j], HID, wmma::mem_row_major);
}

// ---------------- GATv2: one warp per dst, depth-2 pipeline, f32x2 packed math ----------------
__global__ void __launch_bounds__(256)
k_gat(const float* __restrict__ att, const float* __restrict__ gbias, int layer)
{
    __shared__ __align__(16) float s_o[8][128];
    int warp = threadIdx.x >> 5;
    int lane = threadIdx.x & 31;
    int v = blockIdx.x * 8 + warp;            // 3750*8 == NN exactly

    const float* Mb = g_M + layer * 512;
    float4 M0 = *(const float4*)(Mb + 0 * HID + lane * 4);
    float4 M1 = *(const float4*)(Mb + 1 * HID + lane * 4);
    float4 M2 = *(const float4*)(Mb + 2 * HID + lane * 4);
    float4 MC = *(const float4*)(Mb + 3 * HID + lane * 4);
    float4 av = *(const float4*)(att + layer * HID + lane * 4);
    float4 xr4 = *(const float4*)(g_xr + (size_t)v * HID + lane * 4);
    float4 base = make_float4(xr4.x + MC.x, xr4.y + MC.y, xr4.z + MC.z, xr4.w + MC.w);

    // packed constants
    u64 M0a = pk2(M0.x, M0.y), M0b = pk2(M0.z, M0.w);
    u64 M1a = pk2(M1.x, M1.y), M1b = pk2(M1.z, M1.w);
    u64 M2a = pk2(M2.x, M2.y), M2b = pk2(M2.z, M2.w);
    u64 basea = pk2(base.x, base.y), baseb = pk2(base.z, base.w);

    float den = 0.f;
    u64 acca = 0ull, accb = 0ull;
    float sa0 = 0.f, sa1 = 0.f, sa2 = 0.f;

    int e0 = g_rowptr[v], e1 = g_rowptr[v + 1];
    int n = e1 - e0;

    #define GAT_EDGE(EDC, XSU)                                                             \
    {                                                                                      \
        sa0 += (EDC).y; sa1 += (EDC).z; sa2 += (EDC).w;                                    \
        u64 ey2 = pk2((EDC).y, (EDC).y);                                                   \
        u64 ez2 = pk2((EDC).z, (EDC).z);                                                   \
        u64 ew2 = pk2((EDC).w, (EDC).w);                                                   \
        u64 za = fma2(ew2, M2a, fma2(ez2, M1a, fma2(ey2, M0a, add2((XSU).x, basea))));     \
        u64 zb = fma2(ew2, M2b, fma2(ez2, M1b, fma2(ey2, M0b, add2((XSU).y, baseb))));     \
        float t0, t1, t2, t3;                                                              \
        upk2(t0, t1, za); upk2(t2, t3, zb);                                                \
        t0 = fmaxf(t0, 0.2f * t0);                                                         \
        t1 = fmaxf(t1, 0.2f * t1);                                                         \
        t2 = fmaxf(t2, 0.2f * t2);                                                         \
        t3 = fmaxf(t3, 0.2f * t3);                                                         \
        float p = fmaf(t0, av.x, fmaf(t1, av.y, fmaf(t2, av.z, t3 * av.w)));               \
        p += __shfl_xor_sync(0xffffffffu, p, 1);                                           \
        p += __shfl_xor_sync(0xffffffffu, p, 2);                                           \
        p += __shfl_xor_sync(0xffffffffu, p, 4);                                           \
        float f = __expf(p);                                                               \
        den += f;                                                                          \
        u64 f2 = pk2(f, f);                                                                \
        acca = fma2(f2, (XSU).x, acca);                                                    \
        accb = fma2(f2, (XSU).y, accb);                                                    \
    }

    float4 edA, edB;
    ulonglong2 xsA, xsB;
    if (n >= 1) {
        edA = __ldg(&g_csr[e0]);
        xsA = *(const ulonglong2*)(g_xl + (size_t)__float_as_int(edA.x) * HID + lane * 4);
    }
    if (n >= 2) {
        edB = __ldg(&g_csr[e0 + 1]);
        xsB = *(const ulonglong2*)(g_xl + (size_t)__float_as_int(edB.x) * HID + lane * 4);
    }
    int e = e0;
    while (e + 2 <= e1) {
        float4 cA = edA, cB = edB;
        ulonglong2 gA = xsA, gB = xsB;
        int rem = e1 - (e + 2);
        if (rem >= 1) {
            edA = __ldg(&g_csr[e + 2]);
            xsA = *(const ulonglong2*)(g_xl + (size_t)__float_as_int(edA.x) * HID + lane * 4);
        }
        if (rem >= 2) {
            edB = __ldg(&g_csr[e + 3]);
            xsB = *(const ulonglong2*)(g_xl + (size_t)__float_as_int(edB.x) * HID + lane * 4);
        }
        GAT_EDGE(cA, gA);
        GAT_EDGE(cB, gB);
        e += 2;
    }
    if (e < e1) {
        GAT_EDGE(edA, xsA);
    }

    // self loop (edge feature = mean of incoming projected attrs)
    {
        float cv = (float)n;
        float rc = 1.0f / fmaxf(cv, 1.0f);
        float4 slc;                                        // pseudo edge coefs
        slc.y = sa0 * rc; slc.z = sa1 * rc; slc.w = sa2 * rc;
        float aCm1 = (n > 0) ? 0.0f : -1.0f;
        ulonglong2 xvu = *(const ulonglong2*)(g_xl + (size_t)v * HID + lane * 4);
        u64 ey2 = pk2(slc.y, slc.y);
        u64 ez2 = pk2(slc.z, slc.z);
        u64 ew2 = pk2(slc.w, slc.w);
        u64 ac2 = pk2(aCm1, aCm1);
        u64 MCa = pk2(MC.x, MC.y), MCb = pk2(MC.z, MC.w);
        u64 za = fma2(ac2, MCa, fma2(ew2, M2a, fma2(ez2, M1a, fma2(ey2, M0a, add2(xvu.x, basea)))));
        u64 zb = fma2(ac2, MCb, fma2(ew2, M2b, fma2(ez2, M1b, fma2(ey2, M0b, add2(xvu.y, baseb)))));
        float t0, t1, t2, t3;
        upk2(t0, t1, za); upk2(t2, t3, zb);
        t0 = fmaxf(t0, 0.2f * t0);
        t1 = fmaxf(t1, 0.2f * t1);
        t2 = fmaxf(t2, 0.2f * t2);
        t3 = fmaxf(t3, 0.2f * t3);
        float p = fmaf(t0, av.x, fmaf(t1, av.y, fmaf(t2, av.z, t3 * av.w)));
        p += __shfl_xor_sync(0xffffffffu, p, 1);
        p += __shfl_xor_sync(0xffffffffu, p, 2);
        p += __shfl_xor_sync(0xffffffffu, p, 4);
        float f = __expf(p);
        den += f;
        u64 f2 = pk2(f, f);
        acca = fma2(f2, xvu.x, acca);
        accb = fma2(f2, xvu.y, accb);
    }
    float inv = 1.0f / (den + 1e-16f);
    float4 gb = *(const float4*)(gbias + layer * HID + lane * 4);
    float a0, a1, a2, a3;
    upk2(a0, a1, acca); upk2(a2, a3, accb);
    float4 o = make_float4(fmaf(a0, inv, gb.x), fmaf(a1, inv, gb.y),
                           fmaf(a2, inv, gb.z), fmaf(a3, inv, gb.w));
    *(float4*)(g_g + (size_t)v * HID + lane * 4) = o;
    #undef GAT_EDGE

    // ---- fused BN statistics: block smem reduce, then sharded atomics ----
    *(float4*)&s_o[warp][lane * 4] = o;
    __syncthreads();
    int t = threadIdx.x;
    if (t < 128) {
        float s = 0.f, s2 = 0.f;
        #pragma unroll
        for (int w = 0; w < 8; w++) {
            float vv = s_o[w][t];
            s += vv; s2 = fmaf(vv, vv, s2);
        }
        int shard = (blockIdx.x & (NSHARD - 1)) * HID + t;
        atomicAdd(&g_bnsum[shard], s);
        atomicAdd(&g_bnsq[shard], s2);
    }
}

// ---------------- h = relu(bn(g)) + h (float4, shard-summing) ----------------
__global__ void k_bnapply(const float* __restrict__ bng, const float* __restrict__ bnb, int layer)
{
    int idx = blockIdx.x * blockDim.x + threadIdx.x;   // over NN*HID/4
    if (idx >= NN * HID / 4) return;
    int cq = idx & 31;                                 // float4 channel group
    float4 sum = make_float4(0.f, 0.f, 0.f, 0.f);
    float4 sq  = make_float4(0.f, 0.f, 0.f, 0.f);
    #pragma unroll
    for (int s = 0; s < NSHARD; s++) {
        float4 a = ((const float4*)g_bnsum)[s * 32 + cq];
        float4 b = ((const float4*)g_bnsq)[s * 32 + cq];
        sum.x += a.x; sum.y += a.y; sum.z += a.z; sum.w += a.w;
        sq.x += b.x; sq.y += b.y; sq.z += b.z; sq.w += b.w;
    }
    int cg = cq * 4;
    const float invN = 1.0f / NN;
    float4 gm = *(const float4*)&bng[layer * HID + cg];
    float4 bt = *(const float4*)&bnb[layer * HID + cg];
    float m0 = sum.x * invN, m1 = sum.y * invN, m2 = sum.z * invN, m3 = sum.w * invN;
    float r0 = rsqrtf(sq.x * invN - m0 * m0 + 1e-5f) * gm.x;
    float r1 = rsqrtf(sq.y * invN - m1 * m1 + 1e-5f) * gm.y;
    float r2 = rsqrtf(sq.z * invN - m2 * m2 + 1e-5f) * gm.z;
    float r3 = rsqrtf(sq.w * invN - m3 * m3 + 1e-5f) * gm.w;
    float4 g4 = *(const float4*)&g_g[idx * 4];
    float4 h4 = *(const float4*)&g_h[idx * 4];
    h4.x += fmaxf(fmaf(g4.x - m0, r0, bt.x), 0.f);
    h4.y += fmaxf(fmaf(g4.y - m1, r1, bt.y), 0.f);
    h4.z += fmaxf(fmaf(g4.z - m2, r2, bt.z), 0.f);
    h4.w += fmaxf(fmaf(g4.w - m3, r3, bt.w), 0.f);
    *(float4*)&g_h[idx * 4] = h4;
}

// ---------------- head: z1 = comb @ r1W + r1b ----------------
__global__ void __launch_bounds__(256)
k_head1(const int* __restrict__ mut, const float* __restrict__ pert,
        const float* __restrict__ r1W, const float* __restrict__ r1b)
{
    __shared__ float comb[64 * 140];
    __shared__ float Ws[137 * 16];
    int tid = threadIdx.x;
    int colbase = blockIdx.x * 16;
    for (int i = tid; i < 64 * 137; i += 256) {
        int b = i / 137, k = i - b * 137;
        float vv = (k < HID) ? g_h[(size_t)mut[b] * HID + k] : pert[b * 9 + (k - HID)];
        comb[b * 140 + k] = vv;
    }
    for (int i = tid; i < 137 * 16; i += 256) {
        int k = i >> 4, c = i & 15;
        Ws[k * 16 + c] = r1W[k * 256 + colbase + c];
    }
    __syncthreads();
    int row = tid >> 2;
    int cq = (tid & 3) * 4;
    float4 accv = *(const float4*)&r1b[colbase + cq];
    for (int k = 0; k < 137; k++) {
        float a = comb[row * 140 + k];
        float4 w = *(const float4*)&Ws[k * 16 + cq];
        accv.x = fmaf(a, w.x, accv.x);
        accv.y = fmaf(a, w.y, accv.y);
        accv.z = fmaf(a, w.z, accv.z);
        accv.w = fmaf(a, w.w, accv.w);
    }
    *(float4*)&g_z1[row * 256 + colbase + cq] = accv;
}

// ---------------- head BN+relu over 64 rows ----------------
__global__ void k_bnrelu_head(float* __restrict__ z, const float* __restrict__ g,
                              const float* __restrict__ b, int cols)
{
    int c = threadIdx.x;
    if (c >= cols) return;
    float s = 0.f, s2 = 0.f;
    for (int r = 0; r < 64; r++) {
        float v = z[r * cols + c];
        s += v; s2 = fmaf(v, v, s2);
    }
    float m = s * (1.f / 64), var = s2 * (1.f / 64) - m * m;
    float rs = rsqrtf(var + 1e-5f) * g[c];
    float bt = b[c];
    for (int r = 0; r < 64; r++)
        z[r * cols + c] = fmaxf(fmaf(z[r * cols + c] - m, rs, bt), 0.f);
}

// ---------------- head: z2 = z1 @ r2W + r2b ----------------
__global__ void __launch_bounds__(256)
k_head2(const float* __restrict__ r2W, const float* __restrict__ r2b)
{
    extern __shared__ float sm[];
    float* z1s = sm;                  // 64 * 260
    float* Ws  = sm + 64 * 260;       // 256 * 16
    int tid = threadIdx.x;
    int colbase = blockIdx.x * 16;
    for (int i = tid; i < 64 * 64; i += 256) {
        int r = i >> 6;
        int kq = (i & 63) * 4;
        *(float4*)&z1s[r * 260 + kq] = *(const float4*)&g_z1[r * 256 + kq];
    }
    for (int i = tid; i < 256 * 16; i += 256) {
        int k = i >> 4, c = i & 15;
        Ws[k * 16 + c] = r2W[k * 128 + colbase + c];
    }
    __syncthreads();
    int row = tid >> 2;
    int cq = (tid & 3) * 4;
    float4 accv = *(const float4*)&r2b[colbase + cq];
    for (int k = 0; k < 256; k++) {
        float a = z1s[row * 260 + k];
        float4 w = *(const float4*)&Ws[k * 16 + cq];
        accv.x = fmaf(a, w.x, accv.x);
        accv.y = fmaf(a, w.y, accv.y);
        accv.z = fmaf(a, w.z, accv.z);
        accv.w = fmaf(a, w.w, accv.w);
    }
    *(float4*)&g_z2[row * 128 + colbase + cq] = accv;
}

// ---------------- head: z3 = relu(z2 @ r3W + r3b); outputs ----------------
__global__ void __launch_bounds__(256)
k_head3(const float* __restrict__ r3W, const float* __restrict__ r3b,
        const float* __restrict__ clsW, const float* __restrict__ clsb,
        const float* __restrict__ regW, const float* __restrict__ regb,
        float* __restrict__ out)
{
    extern __shared__ float sm[];
    float* z2s = sm;                  // 64 * 132
    float* Ws  = sm + 64 * 132;       // 128 * 64
    float* z3  = Ws + 128 * 64;       // 64 * 68
    int tid = threadIdx.x;
    for (int i = tid; i < 64 * 32; i += 256) {
        int r = i >> 5;
        int kq = (i & 31) * 4;
        *(float4*)&z2s[r * 132 + kq] = *(const float4*)&g_z2[r * 128 + kq];
    }
    for (int i = tid; i < 128 * 16; i += 256) {
        int idx4 = i * 4;
        *(float4*)&Ws[idx4] = *(const float4*)&r3W[idx4];
    }
    __syncthreads();
    int row = tid >> 2;
    int cg = (tid & 3) * 16;
    float acc[16];
    #pragma unroll
    for (int j = 0; j < 16; j++) acc[j] = r3b[cg + j];
    for (int k = 0; k < 128; k++) {
        float a = z2s[row * 132 + k];
        #pragma unroll
        for (int j = 0; j < 16; j++)
            acc[j] = fmaf(a, Ws[k * 64 + cg + j], acc[j]);
    }
    #pragma unroll
    for (int j = 0; j < 16; j++) z3[row * 68 + cg + j] = fmaxf(acc[j], 0.f);
    __syncthreads();
    if (tid < 64) {
        int b = tid;
        float c1 = clsb[0], c2 = regb[0];
        for (int k = 0; k < 64; k++) {
            float v = z3[b * 68 + k];
            c1 = fmaf(v, clsW[k], c1);
            c2 = fmaf(v, regW[k], c2);
        }
        out[b * 2 + 0] = c1;
        out[b * 2 + 1] = c2;
    }
}

// ---------------- launch ----------------
extern "C" void kernel_launch(void* const* d_in, const int* in_sizes, int n_in,
                              void* d_out, int out_size)
{
    (void)in_sizes; (void)n_in; (void)out_size;
    const float* x     = (const float*)d_in[0];
    const float* eattr = (const float*)d_in[1];
    const int*   eidx  = (const int*)d_in[2];
    const int*   mut   = (const int*)d_in[3];
    const float* pert  = (const float*)d_in[4];
    const float* npW   = (const float*)d_in[5];
    const float* npB   = (const float*)d_in[6];
    const float* epW   = (const float*)d_in[7];
    const float* epB   = (const float*)d_in[8];
    const float* Wl    = (const float*)d_in[9];
    const float* bl    = (const float*)d_in[10];
    const float* Wr    = (const float*)d_in[11];
    const float* br    = (const float*)d_in[12];
    const float* We    = (const float*)d_in[13];
    const float* att   = (const float*)d_in[14];
    const float* gbias = (const float*)d_in[15];
    const float* bng   = (const float*)d_in[16];
    const float* bnb   = (const float*)d_in[17];
    const float* r1W   = (const float*)d_in[18];
    const float* r1b   = (const float*)d_in[19];
    const float* bn1g  = (const float*)d_in[20];
    const float* bn1b  = (const float*)d_in[21];
    const float* r2W   = (const float*)d_in[22];
    const float* r2b   = (const float*)d_in[23];
    const float* bn2g  = (const float*)d_in[24];
    const float* bn2b  = (const float*)d_in[25];
    const float* r3W   = (const float*)d_in[26];
    const float* r3b   = (const float*)d_in[27];
    const float* clsW  = (const float*)d_in[28];
    const float* clsb  = (const float*)d_in[29];
    const float* regW  = (const float*)d_in[30];
    const float* regb  = (const float*)d_in[31];
    float* out = (float*)d_out;

    void *p_z1, *p_z2;
    cudaGetSymbolAddress(&p_z1, g_z1);
    cudaGetSymbolAddress(&p_z2, g_z2);

    k_node_proj<<<(NN + 31) / 32, 128>>>(x, npW, npB, epW, epB, We);
    k_deg<<<(EE / 4 + 255) / 256, 256>>>(eidx);
    size_t scan_smem = (33792 + 1024) * sizeof(int);
    cudaFuncSetAttribute(k_scan, cudaFuncAttributeMaxDynamicSharedMemorySize, (int)scan_smem);
    k_scan<<<1, 1024, scan_smem>>>();
    k_scatter<<<(EE / 2 + 255) / 256, 256>>>(eidx, eattr);

    for (int l = 0; l < LL; l++) {
        k_gemm<<<dim3(NNP / 128, 1, 2), 256>>>(
            Wl + (size_t)l * HID * HID, bl + l * HID,
            Wr + (size_t)l * HID * HID, br + l * HID);
        k_gat<<<NN / 8, 256>>>(att, gbias, l);
        k_bnapply<<<(NN * HID / 4 + 255) / 256, 256>>>(bng, bnb, l);
    }

    k_head1<<<16, 256>>>(mut, pert, r1W, r1b);
    k_bnrelu_head<<<1, 256>>>((float*)p_z1, bn1g, bn1b, 256);
    size_t smem2 = (64 * 260 + 256 * 16) * sizeof(float);
    cudaFuncSetAttribute(k_head2, cudaFuncAttributeMaxDynamicSharedMemorySize, (int)smem2);
    k_head2<<<8, 256, smem2>>>(r2W, r2b);
    k_bnrelu_head<<<1, 128>>>((float*)p_z2, bn2g, bn2b, 128);
    size_t smem3 = (64 * 132 + 128 * 64 + 64 * 68) * sizeof(float);
    cudaFuncSetAttribute(k_head3, cudaFuncAttributeMaxDynamicSharedMemorySize, (int)smem3);
    k_head3<<<1, 256, smem3>>>(r3W, r3b, clsW, clsb, regW, regb, out);
}

// round 12
// speedup vs baseline: 1.0419x; 1.0419x over previous
#include <cuda_runtime.h>
#include <cuda_bf16.h>
#include <mma.h>
using namespace nvcuda;

#define NN   30000
#define NNP  30080           // padded rows (235 * 128) for unguarded wmma tiles
#define EE   960000
#define HID  128
#define LL   3
#define BB   64
#define NSHARD 16

typedef unsigned long long u64;
__device__ __forceinline__ u64 pk2(float lo, float hi) {
    u64 r; asm("mov.b64 %0, {%1, %2};" : "=l"(r) : "f"(lo), "f"(hi)); return r;
}
__device__ __forceinline__ void upk2(float& lo, float& hi, u64 v) {
    asm("mov.b64 {%0, %1}, %2;" : "=f"(lo), "=f"(hi) : "l"(v));
}
__device__ __forceinline__ u64 fma2(u64 a, u64 b, u64 c) {
    u64 d; asm("fma.rn.f32x2 %0, %1, %2, %3;" : "=l"(d) : "l"(a), "l"(b), "l"(c)); return d;
}
__device__ __forceinline__ u64 add2(u64 a, u64 b) {
    u64 d; asm("add.rn.f32x2 %0, %1, %2;" : "=l"(d) : "l"(a), "l"(b)); return d;
}

// ---------------- device scratch ----------------
__device__ __align__(16) float  g_h[NNP * HID];    // padding rows stay zero
__device__ __align__(16) float  g_xl[NNP * HID];
__device__ __align__(16) float  g_xr[NNP * HID];
__device__ __align__(16) float  g_g[NN * HID];
__device__ __align__(16) int    g_cnt[32768];      // padded for int4 scan
__device__ int    g_rowptr[NN + 1];
__device__ int    g_fill[NN];                      // seeded with row starts by k_scan
__device__ __align__(16) float4 g_csr[EE];
__device__ __align__(16) float  g_M[LL * 4 * HID]; // {ea0,ea1,ea2,const} per layer
__device__ __align__(16) float  g_bnsum[NSHARD * HID];
__device__ __align__(16) float  g_bnsq[NSHARD * HID];
__device__ __align__(16) float  g_z1[BB * 256];
__device__ __align__(16) float  g_z2[BB * 128];

// ---------------- zero g_cnt (head of edge-preproc stream) ----------------
__global__ void k_zerocnt()
{
    int i = blockIdx.x * blockDim.x + threadIdx.x;
    if (i < 32768) g_cnt[i] = 0;
}

// ---------------- h = x @ npW + npB; block 0 also does precM ----------------
__global__ void k_node_proj(const float* __restrict__ x,
                            const float* __restrict__ npW,
                            const float* __restrict__ npB,
                            const float* __restrict__ epW,
                            const float* __restrict__ epB,
                            const float* __restrict__ We)
{
    __shared__ float Ws[28 * HID];
    int tid = threadIdx.x;                    // 128
    for (int i = tid; i < 28 * HID; i += 128) Ws[i] = npW[i];
    __syncthreads();
    float bias = npB[tid];
    int row0 = blockIdx.x * 32;
    for (int r = 0; r < 32; r++) {
        int row = row0 + r;
        if (row >= NN) break;
        const float* xr = x + row * 28;
        float acc = bias;
        #pragma unroll
        for (int k = 0; k < 28; k++) acc = fmaf(__ldg(xr + k), Ws[k * HID + tid], acc);
        g_h[row * HID + tid] = acc;
    }

    // block 0: precompute M[l] = epW @ We[l], const row = epB @ We[l]
    if (blockIdx.x == 0) {
        int c = tid;
        for (int l = 0; l < LL; l++) {
            const float* W = We + l * HID * HID;
            float m0 = 0.f, m1 = 0.f, m2 = 0.f, mc = 0.f;
            for (int k = 0; k < HID; k++) {
                float w = W[k * HID + c];
                m0 = fmaf(epW[0 * HID + k], w, m0);
                m1 = fmaf(epW[1 * HID + k], w, m1);
                m2 = fmaf(epW[2 * HID + k], w, m2);
                mc = fmaf(epB[k], w, mc);
            }
            g_M[l * 512 + 0 * HID + c] = m0;
            g_M[l * 512 + 1 * HID + c] = m1;
            g_M[l * 512 + 2 * HID + c] = m2;
            g_M[l * 512 + 3 * HID + c] = mc;
        }
    }
}

// ---------------- degree histogram: 4 edges/thread via int4 ----------------
__global__ void k_deg(const int* __restrict__ ei)
{
    int e4 = (blockIdx.x * blockDim.x + threadIdx.x) * 4;
    if (e4 >= EE) return;
    int4 d = *(const int4*)&ei[EE + e4];      // dst array is contiguous, 16B aligned
    atomicAdd(&g_cnt[d.x], 1);
    atomicAdd(&g_cnt[d.y], 1);
    atomicAdd(&g_cnt[d.z], 1);
    atomicAdd(&g_cnt[d.w], 1);
}

// ---------------- exclusive scan; also seeds g_fill with row starts ----------------
__global__ void k_scan()
{
    extern __shared__ int sst[];
    int* stage = sst;                         // 33792 ints (padded i + i/32)
    int* part  = sst + 33792;                 // 1024 ints
    int t = threadIdx.x;
    int base = t * 32;
    int vals[32];
    const int4* c4 = (const int4*)&g_cnt[base];
    int s = 0;
    #pragma unroll
    for (int q = 0; q < 8; q++) {
        int4 v = c4[q];
        vals[q * 4 + 0] = v.x; vals[q * 4 + 1] = v.y;
        vals[q * 4 + 2] = v.z; vals[q * 4 + 3] = v.w;
        s += v.x + v.y + v.z + v.w;
    }
    part[t] = s;
    __syncthreads();
    for (int off = 1; off < 1024; off <<= 1) {
        int v = (t >= off) ? part[t - off] : 0;
        __syncthreads();
        part[t] += v;
        __syncthreads();
    }
    int run = (t == 0) ? 0 : part[t - 1];
    #pragma unroll
    for (int q = 0; q < 32; q++) {
        int i = base + q;
        stage[i + (i >> 5)] = run;            // conflict-free scatter
        run += vals[q];
    }
    __syncthreads();
    for (int i = t; i <= NN; i += 1024) {
        int v = stage[i + (i >> 5)];
        g_rowptr[i] = v;
        if (i < NN) g_fill[i] = v;            // seed fill cursor with row start
    }
}

// ---------------- scatter edges into CSR: 2 edges/thread, single atomic each ----------------
__global__ void k_scatter(const int* __restrict__ ei, const float* __restrict__ ea)
{
    int t = blockIdx.x * blockDim.x + threadIdx.x;   // EE/2 threads
    int eA = t;
    int eB = t + EE / 2;
    if (eA >= EE / 2) return;
    int sA = __ldg(&ei[eA]);
    int dA = __ldg(&ei[EE + eA]);
    float a0 = __ldg(&ea[eA * 3 + 0]);
    float a1 = __ldg(&ea[eA * 3 + 1]);
    float a2 = __ldg(&ea[eA * 3 + 2]);
    int sB = __ldg(&ei[eB]);
    int dB = __ldg(&ei[EE + eB]);
    float b0 = __ldg(&ea[eB * 3 + 0]);
    float b1 = __ldg(&ea[eB * 3 + 1]);
    float b2 = __ldg(&ea[eB * 3 + 2]);
    int posA = atomicAdd(&g_fill[dA], 1);
    int posB = atomicAdd(&g_fill[dB], 1);
    g_csr[posA] = make_float4(__int_as_float(sA), a0, a1, a2);
    g_csr[posB] = make_float4(__int_as_float(sB), b0, b1, b2);
}

// ---------------- xl/xr GEMM: tf32 WMMA, 128x128 tile, 8 warps ----------------
__global__ void __launch_bounds__(256)
k_gemm(const float* __restrict__ W0, const float* __restrict__ b0,
       const float* __restrict__ W1, const float* __restrict__ b1)
{
    __shared__ __align__(16) float As[128][40];    // 128 rows x 32 k (tf32 values)
    __shared__ __align__(16) float Bs[32][132];    // 32 k x 128 cols (tf32 values)
    __shared__ __align__(16) float biasS[16][132]; // bias replicated over 16 rows
    const float* W  = blockIdx.z ? W1 : W0;
    const float* bv = blockIdx.z ? b1 : b0;
    float* out = blockIdx.z ? g_xr : g_xl;

    int tid = threadIdx.x;
    int wid = tid >> 5;
    int row0 = blockIdx.x * 128;

    if (blockIdx.x == 0 && blockIdx.z == 0) { // zero bn shard accumulators for this layer
        for (int i = tid; i < NSHARD * HID; i += 256) {
            g_bnsum[i] = 0.f; g_bnsq[i] = 0.f;
        }
    }

    for (int i = tid; i < 16 * 128; i += 256) {
        int r = i >> 7, c = i & 127;
        biasS[r][c] = bv[c];
    }
    __syncthreads();

    int wr = (wid >> 1) * 32;                 // warp row offset within tile
    int wc = (wid & 1) * 64;                  // warp col offset within tile

    wmma::fragment<wmma::accumulator, 16, 16, 8, float> c[2][4];
    #pragma unroll
    for (int i = 0; i < 2; i++)
        #pragma unroll
        for (int j = 0; j < 4; j++)
            wmma::load_matrix_sync(c[i][j], &biasS[0][wc + j * 16], 132, wmma::mem_row_major);

    for (int kb = 0; kb < HID; kb += 32) {
        __syncthreads();                      // previous iteration's frags consumed
        #pragma unroll
        for (int q = 0; q < 4; q++) {         // A: 128 rows x 32 k = 1024 float4
            int idx = tid + q * 256;
            int r = idx >> 3;
            int kk = (idx & 7) << 2;
            float4 v = *(const float4*)&g_h[(size_t)(row0 + r) * HID + kb + kk];
            As[r][kk + 0] = wmma::__float_to_tf32(v.x);
            As[r][kk + 1] = wmma::__float_to_tf32(v.y);
            As[r][kk + 2] = wmma::__float_to_tf32(v.z);
            As[r][kk + 3] = wmma::__float_to_tf32(v.w);
        }
        #pragma unroll
        for (int q = 0; q < 4; q++) {         // B: 32 k x 128 cols = 1024 float4
            int idx = tid + q * 256;
            int kk = idx >> 5;
            int cc = (idx & 31) << 2;
            float4 v = *(const float4*)&W[(kb + kk) * HID + cc];
            Bs[kk][cc + 0] = wmma::__float_to_tf32(v.x);
            Bs[kk][cc + 1] = wmma::__float_to_tf32(v.y);
            Bs[kk][cc + 2] = wmma::__float_to_tf32(v.z);
            Bs[kk][cc + 3] = wmma::__float_to_tf32(v.w);
        }
        __syncthreads();
        #pragma unroll
        for (int ks = 0; ks < 32; ks += 8) {
            wmma::fragment<wmma::matrix_a, 16, 16, 8, wmma::precision::tf32, wmma::row_major> a[2];
            wmma::fragment<wmma::matrix_b, 16, 16, 8, wmma::precision::tf32, wmma::row_major> b[4];
            #pragma unroll
            for (int i = 0; i < 2; i++)
                wmma::load_matrix_sync(a[i], &As[wr + i * 16][ks], 40);
            #pragma unroll
            for (int j = 0; j < 4; j++)
                wmma::load_matrix_sync(b[j], &Bs[ks][wc + j * 16], 132);
            #pragma unroll
            for (int i = 0; i < 2; i++)
                #pragma unroll
                for (int j = 0; j < 4; j++)
                    wmma::mma_sync(c[i][j], a[i], b[j], c[i][j]);
        }
    }
    #pragma unroll
    for (int i = 0; i < 2; i++)
        #pragma unroll
        for (int j = 0; j < 4; j++)
            wmma::store_matrix_sync(&out[(size_t)(row0 + wr + i * 16) * HID + wc + j * 16],
                                    c[i][j], HID, wmma::mem_row_major);
}

// ---------------- GATv2: one warp per dst, depth-2 pipeline, f32x2 packed math ----------------
__global__ void __launch_bounds__(256)
k_gat(const float* __restrict__ att, const float* __restrict__ gbias, int layer)
{
    __shared__ __align__(16) float s_o[8][128];
    int warp = threadIdx.x >> 5;
    int lane = threadIdx.x & 31;
    int v = blockIdx.x * 8 + warp;            // 3750*8 == NN exactly

    const float* Mb = g_M + layer * 512;
    float4 M0 = *(const float4*)(Mb + 0 * HID + lane * 4);
    float4 M1 = *(const float4*)(Mb + 1 * HID + lane * 4);
    float4 M2 = *(const float4*)(Mb + 2 * HID + lane * 4);
    float4 MC = *(const float4*)(Mb + 3 * HID + lane * 4);
    float4 av = *(const float4*)(att + layer * HID + lane * 4);
    float4 xr4 = *(const float4*)(g_xr + (size_t)v * HID + lane * 4);
    float4 base = make_float4(xr4.x + MC.x, xr4.y + MC.y, xr4.z + MC.z, xr4.w + MC.w);

    // packed constants
    u64 M0a = pk2(M0.x, M0.y), M0b = pk2(M0.z, M0.w);
    u64 M1a = pk2(M1.x, M1.y), M1b = pk2(M1.z, M1.w);
    u64 M2a = pk2(M2.x, M2.y), M2b = pk2(M2.z, M2.w);
    u64 basea = pk2(base.x, base.y), baseb = pk2(base.z, base.w);

    float den = 0.f;
    u64 acca = 0ull, accb = 0ull;
    float sa0 = 0.f, sa1 = 0.f, sa2 = 0.f;

    int e0 = g_rowptr[v], e1 = g_rowptr[v + 1];
    int n = e1 - e0;

    #define GAT_EDGE(EDC, XSU)                                                             \
    {                                                                                      \
        sa0 += (EDC).y; sa1 += (EDC).z; sa2 += (EDC).w;                                    \
        u64 ey2 = pk2((EDC).y, (EDC).y);                                                   \
        u64 ez2 = pk2((EDC).z, (EDC).z);                                                   \
        u64 ew2 = pk2((EDC).w, (EDC).w);                                                   \
        u64 za = fma2(ew2, M2a, fma2(ez2, M1a, fma2(ey2, M0a, add2((XSU).x, basea))));     \
        u64 zb = fma2(ew2, M2b, fma2(ez2, M1b, fma2(ey2, M0b, add2((XSU).y, baseb))));     \
        float t0, t1, t2, t3;                                                              \
        upk2(t0, t1, za); upk2(t2, t3, zb);                                                \
        t0 = fmaxf(t0, 0.2f * t0);                                                         \
        t1 = fmaxf(t1, 0.2f * t1);                                                         \
        t2 = fmaxf(t2, 0.2f * t2);                                                         \
        t3 = fmaxf(t3, 0.2f * t3);                                                         \
        float p = fmaf(t0, av.x, fmaf(t1, av.y, fmaf(t2, av.z, t3 * av.w)));               \
        p += __shfl_xor_sync(0xffffffffu, p, 1);                                           \
        p += __shfl_xor_sync(0xffffffffu, p, 2);                                           \
        p += __shfl_xor_sync(0xffffffffu, p, 4);                                           \
        float f = __expf(p);                                                               \
        den += f;                                                                          \
        u64 f2 = pk2(f, f);                                                                \
        acca = fma2(f2, (XSU).x, acca);                                                    \
        accb = fma2(f2, (XSU).y, accb);                                                    \
    }

    float4 edA, edB;
    ulonglong2 xsA, xsB;
    if (n >= 1) {
        edA = __ldg(&g_csr[e0]);
        xsA = *(const ulonglong2*)(g_xl + (size_t)__float_as_int(edA.x) * HID + lane * 4);
    }
    if (n >= 2) {
        edB = __ldg(&g_csr[e0 + 1]);
        xsB = *(const ulonglong2*)(g_xl + (size_t)__float_as_int(edB.x) * HID + lane * 4);
    }
    int e = e0;
    while (e + 2 <= e1) {
        float4 cA = edA, cB = edB;
        ulonglong2 gA = xsA, gB = xsB;
        int rem = e1 - (e + 2);
        if (rem >= 1) {
            edA = __ldg(&g_csr[e + 2]);
            xsA = *(const ulonglong2*)(g_xl + (size_t)__float_as_int(edA.x) * HID + lane * 4);
        }
        if (rem >= 2) {
            edB = __ldg(&g_csr[e + 3]);
            xsB = *(const ulonglong2*)(g_xl + (size_t)__float_as_int(edB.x) * HID + lane * 4);
        }
        GAT_EDGE(cA, gA);
        GAT_EDGE(cB, gB);
        e += 2;
    }
    if (e < e1) {
        GAT_EDGE(edA, xsA);
    }

    // self loop (edge feature = mean of incoming projected attrs)
    {
        float cv = (float)n;
        float rc = 1.0f / fmaxf(cv, 1.0f);
        float4 slc;                                        // pseudo edge coefs
        slc.y = sa0 * rc; slc.z = sa1 * rc; slc.w = sa2 * rc;
        float aCm1 = (n > 0) ? 0.0f : -1.0f;
        ulonglong2 xvu = *(const ulonglong2*)(g_xl + (size_t)v * HID + lane * 4);
        u64 ey2 = pk2(slc.y, slc.y);
        u64 ez2 = pk2(slc.z, slc.z);
        u64 ew2 = pk2(slc.w, slc.w);
        u64 ac2 = pk2(aCm1, aCm1);
        u64 MCa = pk2(MC.x, MC.y), MCb = pk2(MC.z, MC.w);
        u64 za = fma2(ac2, MCa, fma2(ew2, M2a, fma2(ez2, M1a, fma2(ey2, M0a, add2(xvu.x, basea)))));
        u64 zb = fma2(ac2, MCb, fma2(ew2, M2b, fma2(ez2, M1b, fma2(ey2, M0b, add2(xvu.y, baseb)))));
        float t0, t1, t2, t3;
        upk2(t0, t1, za); upk2(t2, t3, zb);
        t0 = fmaxf(t0, 0.2f * t0);
        t1 = fmaxf(t1, 0.2f * t1);
        t2 = fmaxf(t2, 0.2f * t2);
        t3 = fmaxf(t3, 0.2f * t3);
        float p = fmaf(t0, av.x, fmaf(t1, av.y, fmaf(t2, av.z, t3 * av.w)));
        p += __shfl_xor_sync(0xffffffffu, p, 1);
        p += __shfl_xor_sync(0xffffffffu, p, 2);
        p += __shfl_xor_sync(0xffffffffu, p, 4);
        float f = __expf(p);
        den += f;
        u64 f2 = pk2(f, f);
        acca = fma2(f2, xvu.x, acca);
        accb = fma2(f2, xvu.y, accb);
    }
    float inv = 1.0f / (den + 1e-16f);
    float4 gb = *(const float4*)(gbias + layer * HID + lane * 4);
    float a0, a1, a2, a3;
    upk2(a0, a1, acca); upk2(a2, a3, accb);
    float4 o = make_float4(fmaf(a0, inv, gb.x), fmaf(a1, inv, gb.y),
                           fmaf(a2, inv, gb.z), fmaf(a3, inv, gb.w));
    *(float4*)(g_g + (size_t)v * HID + lane * 4) = o;
    #undef GAT_EDGE

    // ---- fused BN statistics: block smem reduce, then sharded atomics ----
    *(float4*)&s_o[warp][lane * 4] = o;
    __syncthreads();
    int t = threadIdx.x;
    if (t < 128) {
        float s = 0.f, s2 = 0.f;
        #pragma unroll
        for (int w = 0; w < 8; w++) {
            float vv = s_o[w][t];
            s += vv; s2 = fmaf(vv, vv, s2);
        }
        int shard = (blockIdx.x & (NSHARD - 1)) * HID + t;
        atomicAdd(&g_bnsum[shard], s);
        atomicAdd(&g_bnsq[shard], s2);
    }
}

// ---------------- h = relu(bn(g)) + h (float4, shard-summing) ----------------
__global__ void k_bnapply(const float* __restrict__ bng, const float* __restrict__ bnb, int layer)
{
    int idx = blockIdx.x * blockDim.x + threadIdx.x;   // over NN*HID/4
    if (idx >= NN * HID / 4) return;
    int cq = idx & 31;                                 // float4 channel group
    float4 sum = make_float4(0.f, 0.f, 0.f, 0.f);
    float4 sq  = make_float4(0.f, 0.f, 0.f, 0.f);
    #pragma unroll
    for (int s = 0; s < NSHARD; s++) {
        float4 a = ((const float4*)g_bnsum)[s * 32 + cq];
        float4 b = ((const float4*)g_bnsq)[s * 32 + cq];
        sum.x += a.x; sum.y += a.y; sum.z += a.z; sum.w += a.w;
        sq.x += b.x; sq.y += b.y; sq.z += b.z; sq.w += b.w;
    }
    int cg = cq * 4;
    const float invN = 1.0f / NN;
    float4 gm = *(const float4*)&bng[layer * HID + cg];
    float4 bt = *(const float4*)&bnb[layer * HID + cg];
    float m0 = sum.x * invN, m1 = sum.y * invN, m2 = sum.z * invN, m3 = sum.w * invN;
    float r0 = rsqrtf(sq.x * invN - m0 * m0 + 1e-5f) * gm.x;
    float r1 = rsqrtf(sq.y * invN - m1 * m1 + 1e-5f) * gm.y;
    float r2 = rsqrtf(sq.z * invN - m2 * m2 + 1e-5f) * gm.z;
    float r3 = rsqrtf(sq.w * invN - m3 * m3 + 1e-5f) * gm.w;
    float4 g4 = *(const float4*)&g_g[idx * 4];
    float4 h4 = *(const float4*)&g_h[idx * 4];
    h4.x += fmaxf(fmaf(g4.x - m0, r0, bt.x), 0.f);
    h4.y += fmaxf(fmaf(g4.y - m1, r1, bt.y), 0.f);
    h4.z += fmaxf(fmaf(g4.z - m2, r2, bt.z), 0.f);
    h4.w += fmaxf(fmaf(g4.w - m3, r3, bt.w), 0.f);
    *(float4*)&g_h[idx * 4] = h4;
}

// ---------------- head: z1 = comb @ r1W + r1b ----------------
__global__ void __launch_bounds__(256)
k_head1(const int* __restrict__ mut, const float* __restrict__ pert,
        const float* __restrict__ r1W, const float* __restrict__ r1b)
{
    __shared__ float comb[64 * 140];
    __shared__ float Ws[137 * 16];
    int tid = threadIdx.x;
    int colbase = blockIdx.x * 16;
    for (int i = tid; i < 64 * 137; i += 256) {
        int b = i / 137, k = i - b * 137;
        float vv = (k < HID) ? g_h[(size_t)mut[b] * HID + k] : pert[b * 9 + (k - HID)];
        comb[b * 140 + k] = vv;
    }
    for (int i = tid; i < 137 * 16; i += 256) {
        int k = i >> 4, c = i & 15;
        Ws[k * 16 + c] = r1W[k * 256 + colbase + c];
    }
    __syncthreads();
    int row = tid >> 2;
    int cq = (tid & 3) * 4;
    float4 accv = *(const float4*)&r1b[colbase + cq];
    for (int k = 0; k < 137; k++) {
        float a = comb[row * 140 + k];
        float4 w = *(const float4*)&Ws[k * 16 + cq];
        accv.x = fmaf(a, w.x, accv.x);
        accv.y = fmaf(a, w.y, accv.y);
        accv.z = fmaf(a, w.z, accv.z);
        accv.w = fmaf(a, w.w, accv.w);
    }
    *(float4*)&g_z1[row * 256 + colbase + cq] = accv;
}

// ---------------- head BN+relu over 64 rows ----------------
__global__ void k_bnrelu_head(float* __restrict__ z, const float* __restrict__ g,
                              const float* __restrict__ b, int cols)
{
    int c = threadIdx.x;
    if (c >= cols) return;
    float s = 0.f, s2 = 0.f;
    for (int r = 0; r < 64; r++) {
        float v = z[r * cols + c];
        s += v; s2 = fmaf(v, v, s2);
    }
    float m = s * (1.f / 64), var = s2 * (1.f / 64) - m * m;
    float rs = rsqrtf(var + 1e-5f) * g[c];
    float bt = b[c];
    for (int r = 0; r < 64; r++)
        z[r * cols + c] = fmaxf(fmaf(z[r * cols + c] - m, rs, bt), 0.f);
}

// ---------------- head: z2 = z1 @ r2W + r2b ----------------
__global__ void __launch_bounds__(256)
k_head2(const float* __restrict__ r2W, const float* __restrict__ r2b)
{
    extern __shared__ float sm[];
    float* z1s = sm;                  // 64 * 260
    float* Ws  = sm + 64 * 260;       // 256 * 16
    int tid = threadIdx.x;
    int colbase = blockIdx.x * 16;
    for (int i = tid; i < 64 * 64; i += 256) {
        int r = i >> 6;
        int kq = (i & 63) * 4;
        *(float4*)&z1s[r * 260 + kq] = *(const float4*)&g_z1[r * 256 + kq];
    }
    for (int i = tid; i < 256 * 16; i += 256) {
        int k = i >> 4, c = i & 15;
        Ws[k * 16 + c] = r2W[k * 128 + colbase + c];
    }
    __syncthreads();
    int row = tid >> 2;
    int cq = (tid & 3) * 4;
    float4 accv = *(const float4*)&r2b[colbase + cq];
    for (int k = 0; k < 256; k++) {
        float a = z1s[row * 260 + k];
        float4 w = *(const float4*)&Ws[k * 16 + cq];
        accv.x = fmaf(a, w.x, accv.x);
        accv.y = fmaf(a, w.y, accv.y);
        accv.z = fmaf(a, w.z, accv.z);
        accv.w = fmaf(a, w.w, accv.w);
    }
    *(float4*)&g_z2[row * 128 + colbase + cq] = accv;
}

// ---------------- head: z3 = relu(z2 @ r3W + r3b); outputs ----------------
__global__ void __launch_bounds__(256)
k_head3(const float* __restrict__ r3W, const float* __restrict__ r3b,
        const float* __restrict__ clsW, const float* __restrict__ clsb,
        const float* __restrict__ regW, const float* __restrict__ regb,
        float* __restrict__ out)
{
    extern __shared__ float sm[];
    float* z2s = sm;                  // 64 * 132
    float* Ws  = sm + 64 * 132;       // 128 * 64
    float* z3  = Ws + 128 * 64;       // 64 * 68
    int tid = threadIdx.x;
    for (int i = tid; i < 64 * 32; i += 256) {
        int r = i >> 5;
        int kq = (i & 31) * 4;
        *(float4*)&z2s[r * 132 + kq] = *(const float4*)&g_z2[r * 128 + kq];
    }
    for (int i = tid; i < 128 * 16; i += 256) {
        int idx4 = i * 4;
        *(float4*)&Ws[idx4] = *(const float4*)&r3W[idx4];
    }
    __syncthreads();
    int row = tid >> 2;
    int cg = (tid & 3) * 16;
    float acc[16];
    #pragma unroll
    for (int j = 0; j < 16; j++) acc[j] = r3b[cg + j];
    for (int k = 0; k < 128; k++) {
        float a = z2s[row * 132 + k];
        #pragma unroll
        for (int j = 0; j < 16; j++)
            acc[j] = fmaf(a, Ws[k * 64 + cg + j], acc[j]);
    }
    #pragma unroll
    for (int j = 0; j < 16; j++) z3[row * 68 + cg + j] = fmaxf(acc[j], 0.f);
    __syncthreads();
    if (tid < 64) {
        int b = tid;
        float c1 = clsb[0], c2 = regb[0];
        for (int k = 0; k < 64; k++) {
            float v = z3[b * 68 + k];
            c1 = fmaf(v, clsW[k], c1);
            c2 = fmaf(v, regW[k], c2);
        }
        out[b * 2 + 0] = c1;
        out[b * 2 + 1] = c2;
    }
}

// ---------------- launch ----------------
extern "C" void kernel_launch(void* const* d_in, const int* in_sizes, int n_in,
                              void* d_out, int out_size)
{
    (void)in_sizes; (void)n_in; (void)out_size;
    const float* x     = (const float*)d_in[0];
    const float* eattr = (const float*)d_in[1];
    const int*   eidx  = (const int*)d_in[2];
    const int*   mut   = (const int*)d_in[3];
    const float* pert  = (const float*)d_in[4];
    const float* npW   = (const float*)d_in[5];
    const float* npB   = (const float*)d_in[6];
    const float* epW   = (const float*)d_in[7];
    const float* epB   = (const float*)d_in[8];
    const float* Wl    = (const float*)d_in[9];
    const float* bl    = (const float*)d_in[10];
    const float* Wr    = (const float*)d_in[11];
    const float* br    = (const float*)d_in[12];
    const float* We    = (const float*)d_in[13];
    const float* att   = (const float*)d_in[14];
    const float* gbias = (const float*)d_in[15];
    const float* bng   = (const float*)d_in[16];
    const float* bnb   = (const float*)d_in[17];
    const float* r1W   = (const float*)d_in[18];
    const float* r1b   = (const float*)d_in[19];
    const float* bn1g  = (const float*)d_in[20];
    const float* bn1b  = (const float*)d_in[21];
    const float* r2W   = (const float*)d_in[22];
    const float* r2b   = (const float*)d_in[23];
    const float* bn2g  = (const float*)d_in[24];
    const float* bn2b  = (const float*)d_in[25];
    const float* r3W   = (const float*)d_in[26];
    const float* r3b   = (const float*)d_in[27];
    const float* clsW  = (const float*)d_in[28];
    const float* clsb  = (const float*)d_in[29];
    const float* regW  = (const float*)d_in[30];
    const float* regb  = (const float*)d_in[31];
    float* out = (float*)d_out;

    void *p_z1, *p_z2;
    cudaGetSymbolAddress(&p_z1, g_z1);
    cudaGetSymbolAddress(&p_z2, g_z2);

    // one-time resources (handles only; captured node set identical every call)
    static cudaStream_t sB = nullptr;
    static cudaEvent_t evFork = nullptr, evJoin = nullptr;
    if (sB == nullptr) {
        cudaStreamCreateWithFlags(&sB, cudaStreamNonBlocking);
        cudaEventCreateWithFlags(&evFork, cudaEventDisableTiming);
        cudaEventCreateWithFlags(&evJoin, cudaEventDisableTiming);
    }

    // fork: edge preprocessing on sB, node projection + gemm(l0) on default
    cudaEventRecord(evFork, 0);
    cudaStreamWaitEvent(sB, evFork, 0);
    k_zerocnt<<<128, 256, 0, sB>>>();
    k_deg<<<(EE / 4 + 255) / 256, 256, 0, sB>>>(eidx);
    size_t scan_smem = (33792 + 1024) * sizeof(int);
    cudaFuncSetAttribute(k_scan, cudaFuncAttributeMaxDynamicSharedMemorySize, (int)scan_smem);
    k_scan<<<1, 1024, scan_smem, sB>>>();
    k_scatter<<<(EE / 2 + 255) / 256, 256, 0, sB>>>(eidx, eattr);
    cudaEventRecord(evJoin, sB);

    k_node_proj<<<(NN + 31) / 32, 128>>>(x, npW, npB, epW, epB, We);
    k_gemm<<<dim3(NNP / 128, 1, 2), 256>>>(Wl, bl, Wr, br);

    // join: gat(l0) needs the CSR
    cudaStreamWaitEvent(0, evJoin, 0);

    for (int l = 0; l < LL; l++) {
        if (l > 0) {
            k_gemm<<<dim3(NNP / 128, 1, 2), 256>>>(
                Wl + (size_t)l * HID * HID, bl + l * HID,
                Wr + (size_t)l * HID * HID, br + l * HID);
        }
        k_gat<<<NN / 8, 256>>>(att, gbias, l);
        k_bnapply<<<(NN * HID / 4 + 255) / 256, 256>>>(bng, bnb, l);
    }

    k_head1<<<16, 256>>>(mut, pert, r1W, r1b);
    k_bnrelu_head<<<1, 256>>>((float*)p_z1, bn1g, bn1b, 256);
    size_t smem2 = (64 * 260 + 256 * 16) * sizeof(float);
    cudaFuncSetAttribute(k_head2, cudaFuncAttributeMaxDynamicSharedMemorySize, (int)smem2);
    k_head2<<<8, 256, smem2>>>(r2W, r2b);
    k_bnrelu_head<<<1, 128>>>((float*)p_z2, bn2g, bn2b, 128);
    size_t smem3 = (64 * 132 + 128 * 64 + 64 * 68) * sizeof(float);
    cudaFuncSetAttribute(k_head3, cudaFuncAttributeMaxDynamicSharedMemorySize, (int)smem3);
    k_head3<<<1, 256, smem3>>>(r3W, r3b, clsW, clsb, regW, regb, out);
}